// round 4
// baseline (speedup 1.0000x reference)
#include <cuda_runtime.h>
#include <math.h>
#include <stdint.h>

#define NN 8192
#define KK 32
#define NT 64                       // 8192/128 tiles per dim
#define NOFF (NT*(NT-1)/2)          // 2016 strictly-upper tiles
#define NTILES (NOFF + NT)          // 2080 partial slots

typedef unsigned long long u64;

#define FMA2(d,a,b,c) asm("fma.rn.f32x2 %0, %1, %2, %3;" : "=l"(d) : "l"(a), "l"(b), "l"(c))
#define PK2(d,lo,hi)  asm("mov.b64 %0, {%1, %2};" : "=l"(d) : "f"(lo), "f"(hi))
#define UPK2(lo,hi,s) asm("mov.b64 {%0, %1}, %2;" : "=f"(lo), "=f"(hi) : "l"(s))
#define CPA16(dst,src) asm volatile("cp.async.cg.shared.global [%0], [%1], 16;" :: "r"(dst), "l"(src))

// ---- scratch (no allocations allowed) ----
__device__ float  d_Wpart[64*KK*KK];    // partial Xs @ expC per 128-chunk
__device__ float  d_Spart[64*KK];       // partial column sums of expC
__device__ float  d_M [KK*KK];          // M = E^T E
__device__ float  d_Ya[KK*NN];          // 2a * M @ X
__device__ float  d_bv[NN];             // beta - a*q
__device__ double d_partSP[NTILES];
__device__ double d_partTA[NTILES];

// ---------- fused prep: softmax(X) chunk + exp(C) chunk + partial W,S ----------
__global__ void k_prep(const float* __restrict__ X, const float* __restrict__ C) {
    __shared__ float xs[KK][132];   // Xs[p][ii]
    __shared__ float ec[KK][132];   // expC[base+ii][k] -> ec[k][ii]
    int blk = blockIdx.x, tid = threadIdx.x;
    int base = blk * 128;

    if (tid < 128) {
        int i = base + tid;
        float v[KK]; float s = 0.f;
#pragma unroll
        for (int p = 0; p < KK; p++) { v[p] = __expf(X[p*NN + i]); s += v[p]; }
        float inv = 1.f / s;
#pragma unroll
        for (int p = 0; p < KK; p++) xs[p][tid] = v[p] * inv;
    } else {
        int r = tid - 128;
        const float4* cp = (const float4*)&C[(base + r)*KK];
#pragma unroll
        for (int c4 = 0; c4 < 8; c4++) {
            float4 v = cp[c4];
            ec[c4*4+0][r] = __expf(v.x);
            ec[c4*4+1][r] = __expf(v.y);
            ec[c4*4+2][r] = __expf(v.z);
            ec[c4*4+3][r] = __expf(v.w);
        }
    }
    __syncthreads();

    if (tid < 32) {
        float s = 0.f;
#pragma unroll 8
        for (int r = 0; r < 128; r++) s += ec[tid][r];
        d_Spart[blk*32 + tid] = s;
    }

    int p = tid >> 3, k0 = (tid & 7) * 4;
    float a0 = 0.f, a1 = 0.f, a2 = 0.f, a3 = 0.f;
#pragma unroll 4
    for (int ii = 0; ii < 128; ii++) {
        float xv = xs[p][ii];
        a0 += xv * ec[k0+0][ii];
        a1 += xv * ec[k0+1][ii];
        a2 += xv * ec[k0+2][ii];
        a3 += xv * ec[k0+3][ii];
    }
    float* out = &d_Wpart[blk*1024 + p*32 + k0];
    out[0] = a0; out[1] = a1; out[2] = a2; out[3] = a3;
}

// ---------- fused: reduce partials, E = W/S, M = E^T E ----------
__global__ void k_wredM() {
    __shared__ float Es[KK*KK];
    __shared__ float Ssm[KK];
    int tid = threadIdx.x;
    float w[4];
#pragma unroll
    for (int c = 0; c < 4; c++) {
        int e = tid*4 + c;
        float s = 0.f;
#pragma unroll 8
        for (int b = 0; b < 64; b++) s += d_Wpart[b*1024 + e];
        w[c] = s;
    }
    if (tid < 32) {
        float s = 0.f;
#pragma unroll 8
        for (int b = 0; b < 64; b++) s += d_Spart[b*32 + tid];
        Ssm[tid] = s;
    }
    __syncthreads();
#pragma unroll
    for (int c = 0; c < 4; c++) {
        int e = tid*4 + c;
        Es[e] = w[c] / Ssm[e & 31];
    }
    __syncthreads();
#pragma unroll
    for (int c = 0; c < 4; c++) {
        int e = tid*4 + c;
        int p = e >> 5, q = e & 31;
        float s = 0.f;
#pragma unroll
        for (int r = 0; r < KK; r++) s += Es[r*KK + p] * Es[r*KK + q];
        d_M[e] = s;
    }
}

// ---------- Ya = 2a*M*X, b = beta - a*q  (warp w handles p in [8w,8w+8)) ----------
__global__ void k_ya(const float* __restrict__ X, const float* __restrict__ beta,
                     const float* __restrict__ a_p) {
    __shared__ __align__(16) float Ms[KK][KK];
    __shared__ float qsm[4][32];
    int tid = threadIdx.x;
    int lane = tid & 31, w = tid >> 5;
    for (int idx = tid; idx < KK*KK; idx += 128)
        Ms[idx >> 5][idx & 31] = d_M[idx];
    __syncthreads();

    int i = blockIdx.x * 32 + lane;
    float a = a_p[0];
    float twoa = 2.f * a;
    float xv[KK];
#pragma unroll
    for (int q = 0; q < KK; q++) xv[q] = X[q*NN + i];

    float qp = 0.f;
#pragma unroll
    for (int pp = 0; pp < 8; pp++) {
        int p = w*8 + pp;
        const float4* mrow = (const float4*)&Ms[p][0];   // broadcast LDS.128
        float tp = 0.f;
#pragma unroll
        for (int q4 = 0; q4 < 8; q4++) {
            float4 m = mrow[q4];
            tp += m.x * xv[q4*4+0] + m.y * xv[q4*4+1]
                + m.z * xv[q4*4+2] + m.w * xv[q4*4+3];
        }
        d_Ya[p*NN + i] = twoa * tp;
        qp += xv[p] * tp;
    }
    qsm[w][lane] = qp;
    __syncthreads();
    if (w == 0) {
        float qf = qsm[0][lane] + qsm[1][lane] + qsm[2][lane] + qsm[3][lane];
        d_bv[i] = beta[i] - a * qf;
    }
}

__device__ __forceinline__ float softplusf(float x) {
    return fmaxf(x, 0.f) + __logf(1.f + __expf(-fabsf(x)));
}

// ---------- off-diagonal tiles (I<J), 2016 blocks; dynamic smem ----------
// layout: Xt 16KB | Yt 16KB | Asm 64KB | bI 512B | bJ 512B | wSP 32B | wTA 32B
#define OFF_SMEM (16384 + 16384 + 65536 + 512 + 512 + 32 + 32)

__global__ void __launch_bounds__(256, 2)
k_pairs_off(const float* __restrict__ X, const float* __restrict__ A) {
    extern __shared__ char dynsm[];
    float (*Xt)[128]  = (float(*)[128])(dynsm);
    float (*Yt)[128]  = (float(*)[128])(dynsm + 16384);
    float (*Asm)[128] = (float(*)[128])(dynsm + 32768);
    float* bI  = (float*)(dynsm + 98304);
    float* bJ  = bI + 128;
    float* wSP = bJ + 128;
    float* wTA = wSP + 8;

    int t = blockIdx.x;
    int I = 0;
    { int rem = t, rl = NT - 1; while (rem >= rl) { rem -= rl; rl--; I++; } t = rem; }
    int J = I + 1 + t;
    int iBase = I * 128, jBase = J * 128;
    int tid = threadIdx.x;

    // stage the direct A block (rows iBase.., cols jBase..) into smem via cp.async
    {
        uint32_t abase = (uint32_t)__cvta_generic_to_shared(&Asm[0][0]);
#pragma unroll
        for (int c = 0; c < 16; c++) {
            int idx = c*256 + tid;                 // 16B chunk id
            int row = idx >> 5, col16 = idx & 31;  // 32 chunks per 512B row
            const float* src = &A[(u64)(iBase + row)*NN + jBase + col16*4];
            CPA16(abase + row*512 + col16*16, src);
        }
        asm volatile("cp.async.commit_group;");
    }

    // stage X/Ya tiles + biases
#pragma unroll
    for (int c = 0; c < 4; c++) {
        int e = c*1024 + tid*4;
        int p = e >> 7, ii = e & 127;
        *(float4*)&Xt[p][ii] = *(const float4*)&X   [p*NN + iBase + ii];
        *(float4*)&Yt[p][ii] = *(const float4*)&d_Ya[p*NN + jBase + ii];
    }
    if (tid < 128) bI[tid] = d_bv[iBase + tid];
    else           bJ[tid - 128] = d_bv[jBase + tid - 128];
    __syncthreads();

    int tx = tid & 15, ty = tid >> 4;
    float bIr[8], bJc[8];
#pragma unroll
    for (int r = 0; r < 8; r++) bIr[r] = bI[ty*8 + r];
#pragma unroll
    for (int c = 0; c < 4; c++) { bJc[c] = bJ[tx*4 + c]; bJc[c+4] = bJ[64 + tx*4 + c]; }

    u64 acc2[8][4];
#pragma unroll
    for (int r = 0; r < 8; r++)
#pragma unroll
        for (int cp = 0; cp < 4; cp++)
            PK2(acc2[r][cp], bIr[r] + bJc[2*cp], bIr[r] + bJc[2*cp + 1]);

#pragma unroll
    for (int k = 0; k < KK; k++) {
        float4 xa = *(float4*)&Xt[k][ty*8];
        float4 xb = *(float4*)&Xt[k][ty*8 + 4];
        const u64* yp0 = (const u64*)&Yt[k][tx*4];
        const u64* yp1 = (const u64*)&Yt[k][64 + tx*4];
        u64 y2[4] = {yp0[0], yp0[1], yp1[0], yp1[1]};
        float xf[8] = {xa.x, xa.y, xa.z, xa.w, xb.x, xb.y, xb.z, xb.w};
#pragma unroll
        for (int r = 0; r < 8; r++) {
            u64 xx;
            PK2(xx, xf[r], xf[r]);
#pragma unroll
            for (int cp = 0; cp < 4; cp++)
                FMA2(acc2[r][cp], xx, y2[cp], acc2[r][cp]);
        }
    }
    // theta in acc2

    asm volatile("cp.async.wait_group 0;");
    __syncthreads();

    float sSP = 0.f, sTA = 0.f;
    u64 sTA2; PK2(sTA2, 0.f, 0.f);

    // transposed A block first (LDG; unrolled so the compiler batches loads)
#pragma unroll
    for (int c = 0; c < 8; c++) {
        int gj = jBase + ((c < 4) ? (tx*4 + c) : (64 + tx*4 + (c - 4)));
        float4 b0 = __ldcs((const float4*)&A[(u64)gj*NN + iBase + ty*8]);
        float4 b1 = __ldcs((const float4*)&A[(u64)gj*NN + iBase + ty*8 + 4]);
        float atv[8] = {b0.x, b0.y, b0.z, b0.w, b1.x, b1.y, b1.z, b1.w};
        int cp = c >> 1;
#pragma unroll
        for (int r = 0; r < 8; r++) {
            float t0, t1;
            UPK2(t0, t1, acc2[r][cp]);
            sTA += ((c & 1) ? t1 : t0) * atv[r];
        }
    }

    // direct A block from smem + softplus
#pragma unroll
    for (int r = 0; r < 8; r++) {
        int row = ty*8 + r;
        float4 a0 = *(const float4*)&Asm[row][tx*4];
        float4 a1 = *(const float4*)&Asm[row][64 + tx*4];
        u64 a2[4];
        PK2(a2[0], a0.x, a0.y); PK2(a2[1], a0.z, a0.w);
        PK2(a2[2], a1.x, a1.y); PK2(a2[3], a1.z, a1.w);
#pragma unroll
        for (int cp = 0; cp < 4; cp++) {
            float t0, t1;
            UPK2(t0, t1, acc2[r][cp]);
            sSP += softplusf(t0) + softplusf(t1);
            FMA2(sTA2, acc2[r][cp], a2[cp], sTA2);
        }
    }
    sSP *= 2.f;
    {
        float t0, t1;
        UPK2(t0, t1, sTA2);
        sTA += t0 + t1;
    }

#pragma unroll
    for (int o = 16; o > 0; o >>= 1) {
        sSP += __shfl_xor_sync(0xffffffffu, sSP, o);
        sTA += __shfl_xor_sync(0xffffffffu, sTA, o);
    }
    int wid = tid >> 5, lane = tid & 31;
    if (lane == 0) { wSP[wid] = sSP; wTA[wid] = sTA; }
    __syncthreads();
    if (tid == 0) {
        float s1 = 0.f, s2 = 0.f;
#pragma unroll
        for (int w = 0; w < 8; w++) { s1 += wSP[w]; s2 += wTA[w]; }
        d_partSP[blockIdx.x] = (double)s1;
        d_partTA[blockIdx.x] = (double)s2;
    }
}

// ---------- diagonal tiles (I==J), 64 blocks; static smem ----------
__global__ void __launch_bounds__(256, 2)
k_pairs_diag(const float* __restrict__ X, const float* __restrict__ A) {
    __shared__ float Xt[KK][128], Yt[KK][128], bI[128], bJ[128];
    __shared__ float wSP[8], wTA[8];
    int I = blockIdx.x;
    int iBase = I * 128, jBase = iBase;
    int tid = threadIdx.x;

#pragma unroll
    for (int c = 0; c < 4; c++) {
        int e = c*1024 + tid*4;
        int p = e >> 7, ii = e & 127;
        *(float4*)&Xt[p][ii] = *(const float4*)&X   [p*NN + iBase + ii];
        *(float4*)&Yt[p][ii] = *(const float4*)&d_Ya[p*NN + jBase + ii];
    }
    if (tid < 128) bI[tid] = d_bv[iBase + tid];
    else           bJ[tid - 128] = d_bv[jBase + tid - 128];
    __syncthreads();

    int tx = tid & 15, ty = tid >> 4;
    float bIr[8], bJc[8];
#pragma unroll
    for (int r = 0; r < 8; r++) bIr[r] = bI[ty*8 + r];
#pragma unroll
    for (int c = 0; c < 4; c++) { bJc[c] = bJ[tx*4 + c]; bJc[c+4] = bJ[64 + tx*4 + c]; }

    u64 acc2[8][4];
#pragma unroll
    for (int r = 0; r < 8; r++)
#pragma unroll
        for (int cp = 0; cp < 4; cp++)
            PK2(acc2[r][cp], bIr[r] + bJc[2*cp], bIr[r] + bJc[2*cp + 1]);

#pragma unroll
    for (int k = 0; k < KK; k++) {
        float4 xa = *(float4*)&Xt[k][ty*8];
        float4 xb = *(float4*)&Xt[k][ty*8 + 4];
        const u64* yp0 = (const u64*)&Yt[k][tx*4];
        const u64* yp1 = (const u64*)&Yt[k][64 + tx*4];
        u64 y2[4] = {yp0[0], yp0[1], yp1[0], yp1[1]};
        float xf[8] = {xa.x, xa.y, xa.z, xa.w, xb.x, xb.y, xb.z, xb.w};
#pragma unroll
        for (int r = 0; r < 8; r++) {
            u64 xx;
            PK2(xx, xf[r], xf[r]);
#pragma unroll
            for (int cp = 0; cp < 4; cp++)
                FMA2(acc2[r][cp], xx, y2[cp], acc2[r][cp]);
        }
    }

    float sSP = 0.f, sTA = 0.f;
#pragma unroll
    for (int r = 0; r < 8; r++) {
        int gi = iBase + ty*8 + r;
        float4 a0 = __ldcs((const float4*)&A[(u64)gi*NN + jBase + tx*4]);
        float4 a1 = __ldcs((const float4*)&A[(u64)gi*NN + jBase + 64 + tx*4]);
        float av[8] = {a0.x, a0.y, a0.z, a0.w, a1.x, a1.y, a1.z, a1.w};
#pragma unroll
        for (int c = 0; c < 8; c++) {
            int gj = jBase + ((c < 4) ? (tx*4 + c) : (64 + tx*4 + (c - 4)));
            float t0, t1;
            UPK2(t0, t1, acc2[r][c >> 1]);
            float th = (c & 1) ? t1 : t0;
            if (gi < gj) {
                sSP += 2.f * softplusf(th);
                sTA += th * av[c];
            } else if (gi == gj) {
                sTA += th * av[c];
            }
        }
    }
#pragma unroll
    for (int c = 0; c < 8; c++) {
        int gj = jBase + ((c < 4) ? (tx*4 + c) : (64 + tx*4 + (c - 4)));
        float4 b0 = __ldcs((const float4*)&A[(u64)gj*NN + iBase + ty*8]);
        float4 b1 = __ldcs((const float4*)&A[(u64)gj*NN + iBase + ty*8 + 4]);
        float atv[8] = {b0.x, b0.y, b0.z, b0.w, b1.x, b1.y, b1.z, b1.w};
#pragma unroll
        for (int r = 0; r < 8; r++) {
            int gi = iBase + ty*8 + r;
            float t0, t1;
            UPK2(t0, t1, acc2[r][c >> 1]);
            float th = (c & 1) ? t1 : t0;
            if (gi < gj) sTA += th * atv[r];
        }
    }

#pragma unroll
    for (int o = 16; o > 0; o >>= 1) {
        sSP += __shfl_xor_sync(0xffffffffu, sSP, o);
        sTA += __shfl_xor_sync(0xffffffffu, sTA, o);
    }
    int wid = tid >> 5, lane = tid & 31;
    if (lane == 0) { wSP[wid] = sSP; wTA[wid] = sTA; }
    __syncthreads();
    if (tid == 0) {
        float s1 = 0.f, s2 = 0.f;
#pragma unroll
        for (int w = 0; w < 8; w++) { s1 += wSP[w]; s2 += wTA[w]; }
        d_partSP[NOFF + I] = (double)s1;
        d_partTA[NOFF + I] = (double)s2;
    }
}

// ---------- deterministic final reduction ----------
__global__ void k_final(float* __restrict__ out) {
    __shared__ double rSP[256], rTA[256];
    int t = threadIdx.x;
    double s1 = 0.0, s2 = 0.0;
    for (int i = t; i < NTILES; i += 256) { s1 += d_partSP[i]; s2 += d_partTA[i]; }
    rSP[t] = s1; rTA[t] = s2; __syncthreads();
    for (int s = 128; s > 0; s >>= 1) {
        if (t < s) { rSP[t] += rSP[t+s]; rTA[t] += rTA[t+s]; }
        __syncthreads();
    }
    if (t == 0) out[0] = (float)(0.5 * rTA[0] - 0.5 * rSP[0]);
}

extern "C" void kernel_launch(void* const* d_in, const int* in_sizes, int n_in,
                              void* d_out, int out_size) {
    const float* A    = (const float*)d_in[0];
    const float* beta = (const float*)d_in[1];
    const float* a    = (const float*)d_in[2];
    const float* X    = (const float*)d_in[3];
    const float* C    = (const float*)d_in[4];
    float* out = (float*)d_out;

    cudaFuncSetAttribute(k_pairs_off, cudaFuncAttributeMaxDynamicSharedMemorySize, OFF_SMEM);

    k_prep<<<64, 256>>>(X, C);                       // 1
    k_wredM<<<1, 256>>>();                           // 2
    k_ya<<<NN/32, 128>>>(X, beta, a);                // 3
    k_pairs_off<<<NOFF, 256, OFF_SMEM>>>(X, A);      // 4  <- profiled slot
    k_pairs_diag<<<NT, 256>>>(X, A);                 // 5
    k_final<<<1, 256>>>(out);                        // 6
}